// round 11
// baseline (speedup 1.0000x reference)
#include <cuda_runtime.h>
#include <cuda_fp16.h>

// BezierAlign, GB300 (sm_103a).
// input  [2,256,160,160] f32 NCHW,  rois [256,17] f32,  out [256,256,16,64] f32.
//
// Pass 1: NCHW f32 -> NHWC fp16 scratch.
// Pass 2: block = 16 positions, warp per position. Lane 0 of each warp
//         computes the geometry and emits a compact pixel list (byte offset,
//         premultiplied weight); __syncwarp only before the gather. Warp
//         gathers 256 channels, one LDG.128 per pixel, unroll 8. Output is
//         staged in smem with a bank-swizzled layout (col ^= (row&8)<<1,
//         stride 260 so float4 rows stay 16B-aligned) making the transposed
//         read phase bank-conflict-free, then stored coalesced to NCHW.

namespace {

constexpr int OUT_H = 16;
constexpr int OUT_W = 64;
constexpr int C_    = 256;
constexpr int H_    = 160;
constexpr int W_    = 160;
constexpr int HW_   = H_ * W_;
constexpr int R_    = 256;
constexpr float SPATIAL_SCALE = 0.25f;
constexpr int POS_PER_BLK = 16;
constexpr int SOUT_STRIDE = C_ + 4;   // 260 floats = 1040B, 16B-aligned rows

} // namespace

// 26.2 MB NHWC fp16 scratch: [N][H*W][C]
__device__ __align__(16) __half g_nhwc[2 * HW_ * C_];

namespace {

// ---------------------------------------------------------------------------
// Pass 1: NCHW f32 -> NHWC fp16
// ---------------------------------------------------------------------------
__global__ void __launch_bounds__(256)
transpose_kernel(const float* __restrict__ in)
{
    __shared__ float tile[32][33];
    int n   = blockIdx.z;
    int hw0 = blockIdx.x * 32;
    int c0  = blockIdx.y * 32;
    int t   = threadIdx.x;

    {
        int ci = t >> 3;
        int hv = (t & 7) * 4;
        float4 v = *reinterpret_cast<const float4*>(
            in + ((size_t)n * C_ + c0 + ci) * HW_ + hw0 + hv);
        tile[ci][hv + 0] = v.x;
        tile[ci][hv + 1] = v.y;
        tile[ci][hv + 2] = v.z;
        tile[ci][hv + 3] = v.w;
    }
    __syncthreads();
    {
        int hwi = t >> 3;
        int cv  = (t & 7) * 4;
        __half2 h0 = __floats2half2_rn(tile[cv + 0][hwi], tile[cv + 1][hwi]);
        __half2 h1 = __floats2half2_rn(tile[cv + 2][hwi], tile[cv + 3][hwi]);
        uint2 o;
        o.x = *reinterpret_cast<unsigned int*>(&h0);
        o.y = *reinterpret_cast<unsigned int*>(&h1);
        *reinterpret_cast<uint2*>(
            g_nhwc + ((size_t)n * HW_ + hw0 + hwi) * C_ + c0 + cv) = o;
    }
}

// ---------------------------------------------------------------------------
// Pass 2: gather
// ---------------------------------------------------------------------------
__device__ __forceinline__ float bez(float p0, float p1, float p2, float p3, float t) {
    float mt = 1.0f - t;
    return mt*mt*mt*p0 + 3.0f*t*mt*mt*p1 + 3.0f*t*t*mt*p2 + t*t*t*p3;
}

struct DimS { int lo, hi; float wlo, whi; };

__device__ __forceinline__ DimS samp(float coord, int LIMIT) {
    bool valid = (coord > -1.0f) && (coord < (float)LIMIT);
    float c = fmaxf(coord, 0.0f);
    int lo = min((int)floorf(c), LIMIT - 1);
    int hi = min(lo + 1, LIMIT - 1);
    if (lo >= LIMIT - 1) c = (float)lo;
    float l = c - (float)lo;
    float h = 1.0f - l;
    if (!valid) { l = 0.0f; h = 0.0f; }
    DimS d; d.lo = lo; d.hi = hi; d.wlo = h; d.whi = l;
    return d;
}

__device__ __forceinline__ void merge2(const DimS& a, const DimS& b,
                                       int cs[4], float cw[4]) {
    if (b.lo == a.lo) {
        cs[0] = a.lo; cw[0] = a.wlo + b.wlo;
        cs[1] = a.hi; cw[1] = a.whi + b.whi;
        cs[2] = a.lo; cw[2] = 0.0f;
        cs[3] = a.lo; cw[3] = 0.0f;
    } else if (b.lo == a.hi) {
        cs[0] = a.lo; cw[0] = a.wlo;
        cs[1] = a.hi; cw[1] = a.whi + b.wlo;
        cs[2] = b.hi; cw[2] = b.whi;
        cs[3] = a.lo; cw[3] = 0.0f;
    } else {
        cs[0] = a.lo; cw[0] = a.wlo;
        cs[1] = a.hi; cw[1] = a.whi;
        cs[2] = b.lo; cw[2] = b.wlo;
        cs[3] = b.hi; cw[3] = b.whi;
    }
}

__global__ void __launch_bounds__(POS_PER_BLK * 32, 3)
gather_kernel(const float* __restrict__ rois, float* __restrict__ out)
{
    __shared__ int2  s_pix[POS_PER_BLK][16];
    __shared__ __align__(16) float s_out[POS_PER_BLK][SOUT_STRIDE];

    int bid = blockIdx.x;
    int r   = bid >> 6;
    int rem = bid & 63;
    int oh  = rem >> 2;
    int ow0 = (rem & 3) << 4;

    int tid  = threadIdx.x;
    int warp = tid >> 5;
    int lane = tid & 31;

    // ---- geometry: lane 0 of each warp, warp-private list ------------------
    int n = 0;
    if (lane == 0) {
        int ow = ow0 + warp;
        const float* roi = rois + r * 17;
        int bi = (int)__ldg(roi);

        float px[8], py[8];
#pragma unroll
        for (int k = 0; k < 8; ++k) {
            px[k] = __ldg(roi + 1 + 2 * k) * SPATIAL_SCALE;
            py[k] = __ldg(roi + 2 + 2 * k) * SPATIAL_SCALE;
        }

        float u = (float)ow * (1.0f / OUT_W);
        float v = (float)oh * (1.0f / OUT_H);

        float x0 = bez(px[0], px[1], px[2], px[3], u);
        float y0 = bez(py[0], py[1], py[2], py[3], u);
        float x1 = bez(px[4], px[5], px[6], px[7], u);
        float y1 = bez(py[4], py[5], py[6], py[7], u);

        float xc = x1 * v + x0 * (1.0f - v) - 0.5f;   // ALIGNED offset
        float yc = y1 * v + y0 * (1.0f - v) - 0.5f;

        float roi_w = fmaxf(fabsf(px[0] - px[3]), fabsf(px[4] - px[7]));
        float roi_h = fmaxf(fabsf(py[0] - py[3]), fabsf(py[4] - py[7]));
        float bin_h = roi_h * (1.0f / OUT_H);
        float bin_w = roi_w * (1.0f / OUT_W);

        float ya = yc - 0.25f * bin_h;
        float yb = yc + 0.25f * bin_h;
        float xa = xc - 0.25f * bin_w;
        float xb = xc + 0.25f * bin_w;

        DimS sya = samp(ya, H_), syb = samp(yb, H_);
        DimS sxa = samp(xa, W_), sxb = samp(xb, W_);

        int   ycs[4], xcs[4];
        float ywt[4], xwt[4];
        merge2(sya, syb, ycs, ywt);
        merge2(sxa, sxb, xcs, xwt);

        int base_bi = bi * (HW_ * C_ * 2);           // byte offset
#pragma unroll
        for (int iy = 0; iy < 4; ++iy) {
            float wy = ywt[iy];
            if (wy == 0.0f) continue;
            int rowoff = base_bi + ycs[iy] * (W_ * C_ * 2);
#pragma unroll
            for (int ix = 0; ix < 4; ++ix) {
                float wp = wy * xwt[ix];
                if (wp == 0.0f) continue;
                s_pix[warp][n] = make_int2(rowoff + xcs[ix] * (C_ * 2),
                                           __float_as_int(wp * 0.25f));
                ++n;
            }
        }
    }
    __syncwarp();
    int npix = __shfl_sync(0xffffffffu, n, 0);

    // ---- gather: lane = 8 channels (one LDG.128 per pixel) -----------------
    const char* basep = reinterpret_cast<const char*>(g_nhwc) + lane * 16;

    float acc0 = 0.f, acc1 = 0.f, acc2 = 0.f, acc3 = 0.f;
    float acc4 = 0.f, acc5 = 0.f, acc6 = 0.f, acc7 = 0.f;

#pragma unroll 8
    for (int i = 0; i < npix; ++i) {
        int2  pw = s_pix[warp][i];
        float wp = __int_as_float(pw.y);
        uint4 raw = *reinterpret_cast<const uint4*>(basep + pw.x);
        float2 f0 = __half22float2(*reinterpret_cast<__half2*>(&raw.x));
        float2 f1 = __half22float2(*reinterpret_cast<__half2*>(&raw.y));
        float2 f2 = __half22float2(*reinterpret_cast<__half2*>(&raw.z));
        float2 f3 = __half22float2(*reinterpret_cast<__half2*>(&raw.w));
        acc0 += wp * f0.x;  acc1 += wp * f0.y;
        acc2 += wp * f1.x;  acc3 += wp * f1.y;
        acc4 += wp * f2.x;  acc5 += wp * f2.y;
        acc6 += wp * f3.x;  acc7 += wp * f3.y;
    }

    // bank-swizzled staging write: col ^= (row & 8) << 1  (row = warp)
    {
        int sw  = (warp & 8) << 1;                 // 0 or 16
        int col = (lane * 8) ^ sw;                 // flips bit 4 only; 4-aligned
        *reinterpret_cast<float4*>(&s_out[warp][col]) =
            make_float4(acc0, acc1, acc2, acc3);
        *reinterpret_cast<float4*>(&s_out[warp][col + 4]) =
            make_float4(acc4, acc5, acc6, acc7);
    }

    __syncthreads();

    // ---- coalesced store: out[r][c][oh][ow0..ow0+15] -----------------------
    // Read phase applies the same swizzle: rows 0-7 unswizzled, rows 8-15 use
    // c^16 -> the two half-thread groups hit complementary bank sets.
    {
        int c    = tid >> 1;
        int half = tid & 1;
        int p0   = half * 8;
        int csw  = c ^ (half << 4);                // rows p0..p0+7 share (row&8)
        float4 v0, v1;
        v0.x = s_out[p0 + 0][csw]; v0.y = s_out[p0 + 1][csw];
        v0.z = s_out[p0 + 2][csw]; v0.w = s_out[p0 + 3][csw];
        v1.x = s_out[p0 + 4][csw]; v1.y = s_out[p0 + 5][csw];
        v1.z = s_out[p0 + 6][csw]; v1.w = s_out[p0 + 7][csw];
        float* po = out + ((size_t)r * C_ + c) * (OUT_H * OUT_W)
                        + oh * OUT_W + ow0 + p0;
        reinterpret_cast<float4*>(po)[0] = v0;
        reinterpret_cast<float4*>(po)[1] = v1;
    }
}

} // namespace

extern "C" void kernel_launch(void* const* d_in, const int* in_sizes, int n_in,
                              void* d_out, int out_size) {
    const float* input = (const float*)d_in[0];   // [2,256,160,160] f32
    const float* rois  = (const float*)d_in[1];   // [256,17] f32
    float* out = (float*)d_out;                   // [256,256,16,64] f32

    dim3 tgrid(HW_ / 32, C_ / 32, 2);
    transpose_kernel<<<tgrid, 256>>>(input);

    int nblocks = R_ * OUT_H * (OUT_W / POS_PER_BLK);   // 16384
    gather_kernel<<<nblocks, POS_PER_BLK * 32>>>(rois, out);
}

// round 12
// speedup vs baseline: 1.1719x; 1.1719x over previous
#include <cuda_runtime.h>
#include <cuda_fp16.h>

// BezierAlign, GB300 (sm_103a).
// input  [2,256,160,160] f32 NCHW,  rois [256,17] f32,  out [256,256,16,64] f32.
//
// Pass 1: NCHW f32 -> NHWC fp16 scratch.
// Pass 2: block = 16 positions. Threads 0-15 compute geometry ONCE per block
//         (issue cost amortized across all 16 warps) and emit compact pixel
//         lists (byte offset, premultiplied weight). Warp w gathers 256
//         channels for position w: one LDG.128 per pixel, unroll 8. Output is
//         staged in XOR-bank-swizzled smem (col ^= (warp&8)<<1, stride 260 so
//         float4 rows stay 16B-aligned) -> transposed read phase is
//         bank-conflict-free -> coalesced NCHW stores.

namespace {

constexpr int OUT_H = 16;
constexpr int OUT_W = 64;
constexpr int C_    = 256;
constexpr int H_    = 160;
constexpr int W_    = 160;
constexpr int HW_   = H_ * W_;
constexpr int R_    = 256;
constexpr float SPATIAL_SCALE = 0.25f;
constexpr int POS_PER_BLK = 16;
constexpr int SOUT_STRIDE = C_ + 4;   // 260 floats = 1040B; rows 16B-aligned

} // namespace

// 26.2 MB NHWC fp16 scratch: [N][H*W][C]
__device__ __align__(16) __half g_nhwc[2 * HW_ * C_];

namespace {

// ---------------------------------------------------------------------------
// Pass 1: NCHW f32 -> NHWC fp16
// ---------------------------------------------------------------------------
__global__ void __launch_bounds__(256)
transpose_kernel(const float* __restrict__ in)
{
    __shared__ float tile[32][33];
    int n   = blockIdx.z;
    int hw0 = blockIdx.x * 32;
    int c0  = blockIdx.y * 32;
    int t   = threadIdx.x;

    {
        int ci = t >> 3;
        int hv = (t & 7) * 4;
        float4 v = *reinterpret_cast<const float4*>(
            in + ((size_t)n * C_ + c0 + ci) * HW_ + hw0 + hv);
        tile[ci][hv + 0] = v.x;
        tile[ci][hv + 1] = v.y;
        tile[ci][hv + 2] = v.z;
        tile[ci][hv + 3] = v.w;
    }
    __syncthreads();
    {
        int hwi = t >> 3;
        int cv  = (t & 7) * 4;
        __half2 h0 = __floats2half2_rn(tile[cv + 0][hwi], tile[cv + 1][hwi]);
        __half2 h1 = __floats2half2_rn(tile[cv + 2][hwi], tile[cv + 3][hwi]);
        uint2 o;
        o.x = *reinterpret_cast<unsigned int*>(&h0);
        o.y = *reinterpret_cast<unsigned int*>(&h1);
        *reinterpret_cast<uint2*>(
            g_nhwc + ((size_t)n * HW_ + hw0 + hwi) * C_ + c0 + cv) = o;
    }
}

// ---------------------------------------------------------------------------
// Pass 2: gather
// ---------------------------------------------------------------------------
__device__ __forceinline__ float bez(float p0, float p1, float p2, float p3, float t) {
    float mt = 1.0f - t;
    return mt*mt*mt*p0 + 3.0f*t*mt*mt*p1 + 3.0f*t*t*mt*p2 + t*t*t*p3;
}

struct DimS { int lo, hi; float wlo, whi; };

__device__ __forceinline__ DimS samp(float coord, int LIMIT) {
    bool valid = (coord > -1.0f) && (coord < (float)LIMIT);
    float c = fmaxf(coord, 0.0f);
    int lo = min((int)floorf(c), LIMIT - 1);
    int hi = min(lo + 1, LIMIT - 1);
    if (lo >= LIMIT - 1) c = (float)lo;
    float l = c - (float)lo;
    float h = 1.0f - l;
    if (!valid) { l = 0.0f; h = 0.0f; }
    DimS d; d.lo = lo; d.hi = hi; d.wlo = h; d.whi = l;
    return d;
}

__device__ __forceinline__ void merge2(const DimS& a, const DimS& b,
                                       int cs[4], float cw[4]) {
    if (b.lo == a.lo) {
        cs[0] = a.lo; cw[0] = a.wlo + b.wlo;
        cs[1] = a.hi; cw[1] = a.whi + b.whi;
        cs[2] = a.lo; cw[2] = 0.0f;
        cs[3] = a.lo; cw[3] = 0.0f;
    } else if (b.lo == a.hi) {
        cs[0] = a.lo; cw[0] = a.wlo;
        cs[1] = a.hi; cw[1] = a.whi + b.wlo;
        cs[2] = b.hi; cw[2] = b.whi;
        cs[3] = a.lo; cw[3] = 0.0f;
    } else {
        cs[0] = a.lo; cw[0] = a.wlo;
        cs[1] = a.hi; cw[1] = a.whi;
        cs[2] = b.lo; cw[2] = b.wlo;
        cs[3] = b.hi; cw[3] = b.whi;
    }
}

__global__ void __launch_bounds__(POS_PER_BLK * 32, 3)
gather_kernel(const float* __restrict__ rois, float* __restrict__ out)
{
    __shared__ int2  s_pix[POS_PER_BLK][16];
    __shared__ int   s_n[POS_PER_BLK];
    __shared__ __align__(16) float s_out[POS_PER_BLK][SOUT_STRIDE];

    int bid = blockIdx.x;
    int r   = bid >> 6;
    int rem = bid & 63;
    int oh  = rem >> 2;
    int ow0 = (rem & 3) << 4;

    int tid  = threadIdx.x;
    int warp = tid >> 5;
    int lane = tid & 31;

    // ---- geometry: once per block, threads 0-15 ----------------------------
    if (tid < POS_PER_BLK) {
        int ow = ow0 + tid;
        const float* roi = rois + r * 17;
        int bi = (int)__ldg(roi);

        float px[8], py[8];
#pragma unroll
        for (int k = 0; k < 8; ++k) {
            px[k] = __ldg(roi + 1 + 2 * k) * SPATIAL_SCALE;
            py[k] = __ldg(roi + 2 + 2 * k) * SPATIAL_SCALE;
        }

        float u = (float)ow * (1.0f / OUT_W);
        float v = (float)oh * (1.0f / OUT_H);

        float x0 = bez(px[0], px[1], px[2], px[3], u);
        float y0 = bez(py[0], py[1], py[2], py[3], u);
        float x1 = bez(px[4], px[5], px[6], px[7], u);
        float y1 = bez(py[4], py[5], py[6], py[7], u);

        float xc = x1 * v + x0 * (1.0f - v) - 0.5f;   // ALIGNED offset
        float yc = y1 * v + y0 * (1.0f - v) - 0.5f;

        float roi_w = fmaxf(fabsf(px[0] - px[3]), fabsf(px[4] - px[7]));
        float roi_h = fmaxf(fabsf(py[0] - py[3]), fabsf(py[4] - py[7]));
        float bin_h = roi_h * (1.0f / OUT_H);
        float bin_w = roi_w * (1.0f / OUT_W);

        float ya = yc - 0.25f * bin_h;
        float yb = yc + 0.25f * bin_h;
        float xa = xc - 0.25f * bin_w;
        float xb = xc + 0.25f * bin_w;

        DimS sya = samp(ya, H_), syb = samp(yb, H_);
        DimS sxa = samp(xa, W_), sxb = samp(xb, W_);

        int   ycs[4], xcs[4];
        float ywt[4], xwt[4];
        merge2(sya, syb, ycs, ywt);
        merge2(sxa, sxb, xcs, xwt);

        int base_bi = bi * (HW_ * C_ * 2);           // byte offset
        int n = 0;
#pragma unroll
        for (int iy = 0; iy < 4; ++iy) {
            float wy = ywt[iy];
            if (wy == 0.0f) continue;
            int rowoff = base_bi + ycs[iy] * (W_ * C_ * 2);
#pragma unroll
            for (int ix = 0; ix < 4; ++ix) {
                float wp = wy * xwt[ix];
                if (wp == 0.0f) continue;
                s_pix[tid][n] = make_int2(rowoff + xcs[ix] * (C_ * 2),
                                          __float_as_int(wp * 0.25f));
                ++n;
            }
        }
        s_n[tid] = n;
    }
    __syncthreads();

    // ---- gather: warp per position, lane = 8 channels (1 LDG.128/pixel) ----
    int npix = s_n[warp];
    const char* basep = reinterpret_cast<const char*>(g_nhwc) + lane * 16;

    float acc0 = 0.f, acc1 = 0.f, acc2 = 0.f, acc3 = 0.f;
    float acc4 = 0.f, acc5 = 0.f, acc6 = 0.f, acc7 = 0.f;

#pragma unroll 8
    for (int i = 0; i < npix; ++i) {
        int2  pw = s_pix[warp][i];
        float wp = __int_as_float(pw.y);
        uint4 raw = *reinterpret_cast<const uint4*>(basep + pw.x);
        float2 f0 = __half22float2(*reinterpret_cast<__half2*>(&raw.x));
        float2 f1 = __half22float2(*reinterpret_cast<__half2*>(&raw.y));
        float2 f2 = __half22float2(*reinterpret_cast<__half2*>(&raw.z));
        float2 f3 = __half22float2(*reinterpret_cast<__half2*>(&raw.w));
        acc0 += wp * f0.x;  acc1 += wp * f0.y;
        acc2 += wp * f1.x;  acc3 += wp * f1.y;
        acc4 += wp * f2.x;  acc5 += wp * f2.y;
        acc6 += wp * f3.x;  acc7 += wp * f3.y;
    }

    // bank-swizzled staging write: col ^= (warp & 8) << 1
    {
        int sw  = (warp & 8) << 1;                 // 0 or 16
        int col = (lane * 8) ^ sw;                 // flips bit 4 only; 4-aligned
        *reinterpret_cast<float4*>(&s_out[warp][col]) =
            make_float4(acc0, acc1, acc2, acc3);
        *reinterpret_cast<float4*>(&s_out[warp][col + 4]) =
            make_float4(acc4, acc5, acc6, acc7);
    }

    __syncthreads();

    // ---- coalesced store: out[r][c][oh][ow0..ow0+15] -----------------------
    // Rows 0-7 read unswizzled; rows 8-15 read c^16 -> complementary banks.
    {
        int c    = tid >> 1;
        int half = tid & 1;
        int p0   = half * 8;
        int csw  = c ^ (half << 4);
        float4 v0, v1;
        v0.x = s_out[p0 + 0][csw]; v0.y = s_out[p0 + 1][csw];
        v0.z = s_out[p0 + 2][csw]; v0.w = s_out[p0 + 3][csw];
        v1.x = s_out[p0 + 4][csw]; v1.y = s_out[p0 + 5][csw];
        v1.z = s_out[p0 + 6][csw]; v1.w = s_out[p0 + 7][csw];
        float* po = out + ((size_t)r * C_ + c) * (OUT_H * OUT_W)
                        + oh * OUT_W + ow0 + p0;
        reinterpret_cast<float4*>(po)[0] = v0;
        reinterpret_cast<float4*>(po)[1] = v1;
    }
}

} // namespace

extern "C" void kernel_launch(void* const* d_in, const int* in_sizes, int n_in,
                              void* d_out, int out_size) {
    const float* input = (const float*)d_in[0];   // [2,256,160,160] f32
    const float* rois  = (const float*)d_in[1];   // [256,17] f32
    float* out = (float*)d_out;                   // [256,256,16,64] f32

    dim3 tgrid(HW_ / 32, C_ / 32, 2);
    transpose_kernel<<<tgrid, 256>>>(input);

    int nblocks = R_ * OUT_H * (OUT_W / POS_PER_BLK);   // 16384
    gather_kernel<<<nblocks, POS_PER_BLK * 32>>>(rois, out);
}

// round 13
// speedup vs baseline: 1.2988x; 1.1084x over previous
#include <cuda_runtime.h>
#include <cuda_fp16.h>

// BezierAlign, GB300 (sm_103a).
// input  [2,256,160,160] f32 NCHW,  rois [256,17] f32,  out [256,256,16,64] f32.
//
// Pass 1: NCHW f32 -> NHWC fp16 scratch.
// Pass 2: block = 16 positions. Threads 0-15 compute geometry once per block,
//         emitting pixel lists of (byte offset, fp16x2 weight). Warp w gathers
//         256 channels for position w: per pixel one LDG.128 + 4 HFMA2
//         (half2 accumulation -> fewer instructions AND fewer registers,
//         enabling 4 blocks/SM = 64 warps for latency hiding). f32 conversion
//         happens once at the end; staging via XOR-swizzled smem -> coalesced
//         NCHW stores.

namespace {

constexpr int OUT_H = 16;
constexpr int OUT_W = 64;
constexpr int C_    = 256;
constexpr int H_    = 160;
constexpr int W_    = 160;
constexpr int HW_   = H_ * W_;
constexpr int R_    = 256;
constexpr float SPATIAL_SCALE = 0.25f;
constexpr int POS_PER_BLK = 16;
constexpr int SOUT_STRIDE = C_ + 4;   // 260 floats = 1040B; rows 16B-aligned

} // namespace

// 26.2 MB NHWC fp16 scratch: [N][H*W][C]
__device__ __align__(16) __half g_nhwc[2 * HW_ * C_];

namespace {

// ---------------------------------------------------------------------------
// Pass 1: NCHW f32 -> NHWC fp16
// ---------------------------------------------------------------------------
__global__ void __launch_bounds__(256)
transpose_kernel(const float* __restrict__ in)
{
    __shared__ float tile[32][33];
    int n   = blockIdx.z;
    int hw0 = blockIdx.x * 32;
    int c0  = blockIdx.y * 32;
    int t   = threadIdx.x;

    {
        int ci = t >> 3;
        int hv = (t & 7) * 4;
        float4 v = *reinterpret_cast<const float4*>(
            in + ((size_t)n * C_ + c0 + ci) * HW_ + hw0 + hv);
        tile[ci][hv + 0] = v.x;
        tile[ci][hv + 1] = v.y;
        tile[ci][hv + 2] = v.z;
        tile[ci][hv + 3] = v.w;
    }
    __syncthreads();
    {
        int hwi = t >> 3;
        int cv  = (t & 7) * 4;
        __half2 h0 = __floats2half2_rn(tile[cv + 0][hwi], tile[cv + 1][hwi]);
        __half2 h1 = __floats2half2_rn(tile[cv + 2][hwi], tile[cv + 3][hwi]);
        uint2 o;
        o.x = *reinterpret_cast<unsigned int*>(&h0);
        o.y = *reinterpret_cast<unsigned int*>(&h1);
        *reinterpret_cast<uint2*>(
            g_nhwc + ((size_t)n * HW_ + hw0 + hwi) * C_ + c0 + cv) = o;
    }
}

// ---------------------------------------------------------------------------
// Pass 2: gather
// ---------------------------------------------------------------------------
__device__ __forceinline__ float bez(float p0, float p1, float p2, float p3, float t) {
    float mt = 1.0f - t;
    return mt*mt*mt*p0 + 3.0f*t*mt*mt*p1 + 3.0f*t*t*mt*p2 + t*t*t*p3;
}

struct DimS { int lo, hi; float wlo, whi; };

__device__ __forceinline__ DimS samp(float coord, int LIMIT) {
    bool valid = (coord > -1.0f) && (coord < (float)LIMIT);
    float c = fmaxf(coord, 0.0f);
    int lo = min((int)floorf(c), LIMIT - 1);
    int hi = min(lo + 1, LIMIT - 1);
    if (lo >= LIMIT - 1) c = (float)lo;
    float l = c - (float)lo;
    float h = 1.0f - l;
    if (!valid) { l = 0.0f; h = 0.0f; }
    DimS d; d.lo = lo; d.hi = hi; d.wlo = h; d.whi = l;
    return d;
}

__device__ __forceinline__ void merge2(const DimS& a, const DimS& b,
                                       int cs[4], float cw[4]) {
    if (b.lo == a.lo) {
        cs[0] = a.lo; cw[0] = a.wlo + b.wlo;
        cs[1] = a.hi; cw[1] = a.whi + b.whi;
        cs[2] = a.lo; cw[2] = 0.0f;
        cs[3] = a.lo; cw[3] = 0.0f;
    } else if (b.lo == a.hi) {
        cs[0] = a.lo; cw[0] = a.wlo;
        cs[1] = a.hi; cw[1] = a.whi + b.wlo;
        cs[2] = b.hi; cw[2] = b.whi;
        cs[3] = a.lo; cw[3] = 0.0f;
    } else {
        cs[0] = a.lo; cw[0] = a.wlo;
        cs[1] = a.hi; cw[1] = a.whi;
        cs[2] = b.lo; cw[2] = b.wlo;
        cs[3] = b.hi; cw[3] = b.whi;
    }
}

__global__ void __launch_bounds__(POS_PER_BLK * 32, 4)
gather_kernel(const float* __restrict__ rois, float* __restrict__ out)
{
    __shared__ int2  s_pix[POS_PER_BLK][16];   // (byte offset, half2 weight bits)
    __shared__ int   s_n[POS_PER_BLK];
    __shared__ __align__(16) float s_out[POS_PER_BLK][SOUT_STRIDE];

    int bid = blockIdx.x;
    int r   = bid >> 6;
    int rem = bid & 63;
    int oh  = rem >> 2;
    int ow0 = (rem & 3) << 4;

    int tid  = threadIdx.x;
    int warp = tid >> 5;
    int lane = tid & 31;

    // ---- geometry: once per block, threads 0-15 ----------------------------
    if (tid < POS_PER_BLK) {
        int ow = ow0 + tid;
        const float* roi = rois + r * 17;
        int bi = (int)__ldg(roi);

        float px[8], py[8];
#pragma unroll
        for (int k = 0; k < 8; ++k) {
            px[k] = __ldg(roi + 1 + 2 * k) * SPATIAL_SCALE;
            py[k] = __ldg(roi + 2 + 2 * k) * SPATIAL_SCALE;
        }

        float u = (float)ow * (1.0f / OUT_W);
        float v = (float)oh * (1.0f / OUT_H);

        float x0 = bez(px[0], px[1], px[2], px[3], u);
        float y0 = bez(py[0], py[1], py[2], py[3], u);
        float x1 = bez(px[4], px[5], px[6], px[7], u);
        float y1 = bez(py[4], py[5], py[6], py[7], u);

        float xc = x1 * v + x0 * (1.0f - v) - 0.5f;   // ALIGNED offset
        float yc = y1 * v + y0 * (1.0f - v) - 0.5f;

        float roi_w = fmaxf(fabsf(px[0] - px[3]), fabsf(px[4] - px[7]));
        float roi_h = fmaxf(fabsf(py[0] - py[3]), fabsf(py[4] - py[7]));
        float bin_h = roi_h * (1.0f / OUT_H);
        float bin_w = roi_w * (1.0f / OUT_W);

        float ya = yc - 0.25f * bin_h;
        float yb = yc + 0.25f * bin_h;
        float xa = xc - 0.25f * bin_w;
        float xb = xc + 0.25f * bin_w;

        DimS sya = samp(ya, H_), syb = samp(yb, H_);
        DimS sxa = samp(xa, W_), sxb = samp(xb, W_);

        int   ycs[4], xcs[4];
        float ywt[4], xwt[4];
        merge2(sya, syb, ycs, ywt);
        merge2(sxa, sxb, xcs, xwt);

        int base_bi = bi * (HW_ * C_ * 2);           // byte offset
        int n = 0;
#pragma unroll
        for (int iy = 0; iy < 4; ++iy) {
            float wy = ywt[iy];
            if (wy == 0.0f) continue;
            int rowoff = base_bi + ycs[iy] * (W_ * C_ * 2);
#pragma unroll
            for (int ix = 0; ix < 4; ++ix) {
                float wp = wy * xwt[ix];
                if (wp == 0.0f) continue;
                __half2 w2 = __float2half2_rn(wp * 0.25f);
                s_pix[tid][n] = make_int2(rowoff + xcs[ix] * (C_ * 2),
                                          *reinterpret_cast<int*>(&w2));
                ++n;
            }
        }
        s_n[tid] = n;
    }
    __syncthreads();

    // ---- gather: warp per position, lane = 8 channels; half2 accumulate ----
    int npix = s_n[warp];
    const char* basep = reinterpret_cast<const char*>(g_nhwc) + lane * 16;

    __half2 acc0 = __float2half2_rn(0.f);
    __half2 acc1 = acc0, acc2 = acc0, acc3 = acc0;

#pragma unroll 8
    for (int i = 0; i < npix; ++i) {
        int2    pw  = s_pix[warp][i];
        __half2 wp2 = *reinterpret_cast<__half2*>(&pw.y);
        uint4   raw = *reinterpret_cast<const uint4*>(basep + pw.x);
        acc0 = __hfma2(wp2, *reinterpret_cast<__half2*>(&raw.x), acc0);
        acc1 = __hfma2(wp2, *reinterpret_cast<__half2*>(&raw.y), acc1);
        acc2 = __hfma2(wp2, *reinterpret_cast<__half2*>(&raw.z), acc2);
        acc3 = __hfma2(wp2, *reinterpret_cast<__half2*>(&raw.w), acc3);
    }

    // convert once, write to swizzled staging
    {
        float2 f0 = __half22float2(acc0);
        float2 f1 = __half22float2(acc1);
        float2 f2 = __half22float2(acc2);
        float2 f3 = __half22float2(acc3);
        int sw  = (warp & 8) << 1;                 // 0 or 16
        int col = (lane * 8) ^ sw;                 // flips bit 4 only; 4-aligned
        *reinterpret_cast<float4*>(&s_out[warp][col]) =
            make_float4(f0.x, f0.y, f1.x, f1.y);
        *reinterpret_cast<float4*>(&s_out[warp][col + 4]) =
            make_float4(f2.x, f2.y, f3.x, f3.y);
    }

    __syncthreads();

    // ---- coalesced store: out[r][c][oh][ow0..ow0+15] -----------------------
    {
        int c    = tid >> 1;
        int half = tid & 1;
        int p0   = half * 8;
        int csw  = c ^ (half << 4);
        float4 v0, v1;
        v0.x = s_out[p0 + 0][csw]; v0.y = s_out[p0 + 1][csw];
        v0.z = s_out[p0 + 2][csw]; v0.w = s_out[p0 + 3][csw];
        v1.x = s_out[p0 + 4][csw]; v1.y = s_out[p0 + 5][csw];
        v1.z = s_out[p0 + 6][csw]; v1.w = s_out[p0 + 7][csw];
        float* po = out + ((size_t)r * C_ + c) * (OUT_H * OUT_W)
                        + oh * OUT_W + ow0 + p0;
        reinterpret_cast<float4*>(po)[0] = v0;
        reinterpret_cast<float4*>(po)[1] = v1;
    }
}

} // namespace

extern "C" void kernel_launch(void* const* d_in, const int* in_sizes, int n_in,
                              void* d_out, int out_size) {
    const float* input = (const float*)d_in[0];   // [2,256,160,160] f32
    const float* rois  = (const float*)d_in[1];   // [256,17] f32
    float* out = (float*)d_out;                   // [256,256,16,64] f32

    dim3 tgrid(HW_ / 32, C_ / 32, 2);
    transpose_kernel<<<tgrid, 256>>>(input);

    int nblocks = R_ * OUT_H * (OUT_W / POS_PER_BLK);   // 16384
    gather_kernel<<<nblocks, POS_PER_BLK * 32>>>(rois, out);
}